// round 6
// baseline (speedup 1.0000x reference)
#include <cuda_runtime.h>
#include <math.h>
#include <stdint.h>

#define N_NODES 100000
#define N_EDGES 1600000
#define IN_DIM  256
#define OUT_DIM 64
#define LEAKY   0.01f

#define SCAN_CHUNK 1024
#define NCHUNKS ((N_NODES + SCAN_CHUNK - 1) / SCAN_CHUNK)   // 98

// ---------------- scratch ----------------
__device__ float g_z   [N_NODES * OUT_DIM];   // 25.6 MB (L2-resident)
__device__ float g_el  [N_NODES];
__device__ float g_er  [N_NODES];
__device__ int   g_cnt [N_NODES];
__device__ int   g_off [N_NODES + 1];
__device__ int   g_rank[N_EDGES];             // within-destination rank of each edge
__device__ int   g_csr [N_EDGES];             // src ids, dst-sorted
// decoupled-lookback state
__device__ volatile int g_blk_agg [NCHUNKS];
__device__ volatile int g_blk_incl[NCHUNKS];
__device__ volatile int g_blk_flag[NCHUNKS];  // 0 none, 1 aggregate, 2 inclusive

// ---------------- helpers ----------------
__device__ __forceinline__ float cvt_tf32(float x) {
    uint32_t o;
    asm("cvt.rna.tf32.f32 %0, %1;" : "=r"(o) : "f"(x));
    return __uint_as_float(o);
}

__device__ __forceinline__ float4 cvt_tf32_v4(float4 v) {
    v.x = cvt_tf32(v.x); v.y = cvt_tf32(v.y);
    v.z = cvt_tf32(v.z); v.w = cvt_tf32(v.w);
    return v;
}

__device__ __forceinline__ void mma_tf32(float& d0, float& d1, float& d2, float& d3,
                                         uint32_t a0, uint32_t a1, uint32_t a2, uint32_t a3,
                                         uint32_t b0, uint32_t b1) {
    asm volatile("mma.sync.aligned.m16n8k8.row.col.f32.tf32.tf32.f32 "
                 "{%0,%1,%2,%3}, {%4,%5,%6,%7}, {%8,%9}, {%0,%1,%2,%3};"
                 : "+f"(d0), "+f"(d1), "+f"(d2), "+f"(d3)
                 : "r"(a0), "r"(a1), "r"(a2), "r"(a3), "r"(b0), "r"(b1));
}

// ---------------- K1: tensor-core GEMM (round-4 structure) + fused zeroing ------
// block = 256 threads (8 warps). tile = 128 rows x 64 cols. k-chunks of 32, 2-stage
// register prefetch; cvt to tf32 at stage time (NOT in the mma mainloop).
__global__ void __launch_bounds__(256) k_gemm(const float* __restrict__ h,
                                              const float* __restrict__ W,
                                              const float* __restrict__ a_attn) {
    __shared__ float As[128][36];   // pad 36: conflict-free A frag loads
    __shared__ float Bs[32][72];    // pad 72: conflict-free B frag loads

    const int tid  = threadIdx.x;
    const int warp = tid >> 5;
    const int lane = tid & 31;
    const int m0   = blockIdx.x * 128;
    const int wrow = warp * 16;
    const int r = lane >> 2;        // 0..7
    const int c = lane & 3;         // 0..3

    // fused zeroing for downstream kernels (CSR histogram + lookback flags)
    {
        int gi = blockIdx.x * 256 + tid;
        if (gi < N_NODES) g_cnt[gi] = 0;
        if (gi < NCHUNKS) g_blk_flag[gi] = 0;
    }

    int arow[4], akq[4];
#pragma unroll
    for (int i = 0; i < 4; i++) {
        int id = tid + i * 256;
        arow[i] = id >> 3;
        akq[i]  = id & 7;
    }
    int bkk[2], bnq[2];
#pragma unroll
    for (int i = 0; i < 2; i++) {
        int id = tid + i * 256;
        bkk[i] = id >> 4;
        bnq[i] = id & 15;
    }

    float d[8][4];
#pragma unroll
    for (int j = 0; j < 8; j++)
#pragma unroll
        for (int q = 0; q < 4; q++) d[j][q] = 0.0f;

    float4 ra[4], rb[2];

    // prologue: load chunk 0
#pragma unroll
    for (int i = 0; i < 4; i++) {
        float4 v = make_float4(0.f, 0.f, 0.f, 0.f);
        if (m0 + arow[i] < N_NODES)
            v = *(const float4*)(h + (size_t)(m0 + arow[i]) * IN_DIM + akq[i] * 4);
        ra[i] = cvt_tf32_v4(v);
    }
#pragma unroll
    for (int i = 0; i < 2; i++)
        rb[i] = cvt_tf32_v4(*(const float4*)(W + (size_t)bkk[i] * OUT_DIM + bnq[i] * 4));

    for (int k0 = 0; k0 < IN_DIM; k0 += 32) {
#pragma unroll
        for (int i = 0; i < 4; i++)
            *(float4*)&As[arow[i]][akq[i] * 4] = ra[i];
#pragma unroll
        for (int i = 0; i < 2; i++)
            *(float4*)&Bs[bkk[i]][bnq[i] * 4] = rb[i];
        __syncthreads();

        int kn = k0 + 32;
        if (kn < IN_DIM) {
#pragma unroll
            for (int i = 0; i < 4; i++) {
                float4 v = make_float4(0.f, 0.f, 0.f, 0.f);
                if (m0 + arow[i] < N_NODES)
                    v = *(const float4*)(h + (size_t)(m0 + arow[i]) * IN_DIM + kn + akq[i] * 4);
                ra[i] = cvt_tf32_v4(v);
            }
#pragma unroll
            for (int i = 0; i < 2; i++)
                rb[i] = cvt_tf32_v4(*(const float4*)(W + (size_t)(kn + bkk[i]) * OUT_DIM + bnq[i] * 4));
        }

#pragma unroll
        for (int ks = 0; ks < 32; ks += 8) {
            uint32_t a0 = __float_as_uint(As[wrow + r    ][ks + c    ]);
            uint32_t a1 = __float_as_uint(As[wrow + r + 8][ks + c    ]);
            uint32_t a2 = __float_as_uint(As[wrow + r    ][ks + c + 4]);
            uint32_t a3 = __float_as_uint(As[wrow + r + 8][ks + c + 4]);
#pragma unroll
            for (int j = 0; j < 8; j++) {
                uint32_t b0 = __float_as_uint(Bs[ks + c    ][8 * j + r]);
                uint32_t b1 = __float_as_uint(Bs[ks + c + 4][8 * j + r]);
                mma_tf32(d[j][0], d[j][1], d[j][2], d[j][3], a0, a1, a2, a3, b0, b1);
            }
        }
        __syncthreads();
    }

    // ---- epilogue: store z, compute el/er (rows unique per warp, no atomics) ----
    const int row_lo = m0 + wrow + r;
    const int row_hi = row_lo + 8;

    float pl0 = 0.f, pl1 = 0.f, pr0 = 0.f, pr1 = 0.f;
#pragma unroll
    for (int j = 0; j < 8; j++) {
        int n = 8 * j + 2 * c;
        float al0 = a_attn[n], al1 = a_attn[n + 1];
        float ar0 = a_attn[OUT_DIM + n], ar1 = a_attn[OUT_DIM + n + 1];
        pl0 += d[j][0] * al0 + d[j][1] * al1;
        pr0 += d[j][0] * ar0 + d[j][1] * ar1;
        pl1 += d[j][2] * al0 + d[j][3] * al1;
        pr1 += d[j][2] * ar0 + d[j][3] * ar1;
        if (row_lo < N_NODES)
            *(float2*)(g_z + (size_t)row_lo * OUT_DIM + n) = make_float2(d[j][0], d[j][1]);
        if (row_hi < N_NODES)
            *(float2*)(g_z + (size_t)row_hi * OUT_DIM + n) = make_float2(d[j][2], d[j][3]);
    }
#pragma unroll
    for (int o = 1; o <= 2; o <<= 1) {
        pl0 += __shfl_xor_sync(0xffffffffu, pl0, o);
        pl1 += __shfl_xor_sync(0xffffffffu, pl1, o);
        pr0 += __shfl_xor_sync(0xffffffffu, pr0, o);
        pr1 += __shfl_xor_sync(0xffffffffu, pr1, o);
    }
    if (c == 0) {
        if (row_lo < N_NODES) { g_el[row_lo] = pl0; g_er[row_lo] = pr0; }
        if (row_hi < N_NODES) { g_el[row_hi] = pl1; g_er[row_hi] = pr1; }
    }
}

// ---------------- K2: histogram of dst + edge rank capture ----------------
__global__ void k_hist(const int* __restrict__ dst) {
    int i = blockIdx.x * blockDim.x + threadIdx.x;
    if (i >= N_EDGES) return;
    g_rank[i] = atomicAdd(&g_cnt[dst[i]], 1);
}

// ---------------- K3: single-pass decoupled-lookback scan ----------------
__global__ void __launch_bounds__(SCAN_CHUNK) k_scan() {
    __shared__ int wsum[32];
    __shared__ int s_exc;
    const int tid  = threadIdx.x;
    const int lane = tid & 31;
    const int w    = tid >> 5;
    const int b    = blockIdx.x;
    const int i    = b * SCAN_CHUNK + tid;

    int x = (i < N_NODES) ? g_cnt[i] : 0;
    int v = x;
#pragma unroll
    for (int o = 1; o < 32; o <<= 1) {
        int t = __shfl_up_sync(0xffffffffu, v, o);
        if (lane >= o) v += t;
    }
    if (lane == 31) wsum[w] = v;
    __syncthreads();
    if (w == 0) {
        int y = wsum[lane];
#pragma unroll
        for (int o = 1; o < 32; o <<= 1) {
            int t = __shfl_up_sync(0xffffffffu, y, o);
            if (lane >= o) y += t;
        }
        wsum[lane] = y;   // inclusive warp sums
    }
    __syncthreads();
    int base = (w > 0) ? wsum[w - 1] : 0;
    int incl = v + base;
    int T    = wsum[31];   // block total

    if (tid == 0) {
        if (b == 0) {
            g_blk_incl[0] = T;
            __threadfence();
            g_blk_flag[0] = 2;
            s_exc = 0;
        } else {
            g_blk_agg[b] = T;
            __threadfence();
            g_blk_flag[b] = 1;
            int exc = 0;
            int j = b - 1;
            while (true) {
                int f;
                do { f = g_blk_flag[j]; } while (f == 0);
                __threadfence();
                if (f == 2) { exc += g_blk_incl[j]; break; }
                exc += g_blk_agg[j];
                j--;
            }
            g_blk_incl[b] = exc + T;
            __threadfence();
            g_blk_flag[b] = 2;
            s_exc = exc;
        }
    }
    __syncthreads();
    if (i < N_NODES) g_off[i] = s_exc + incl - x;   // global exclusive prefix
    if (b == NCHUNKS - 1 && tid == SCAN_CHUNK - 1) g_off[N_NODES] = N_EDGES;
}

// ---------------- K4: atomic-free scatter (rank precomputed in hist) ------------
__global__ void k_scatter(const int* __restrict__ src, const int* __restrict__ dst) {
    int i = blockIdx.x * blockDim.x + threadIdx.x;
    if (i >= N_EDGES) return;
    int d = dst[i];
    g_csr[g_off[d] + g_rank[i]] = src[i];
}

// ---------------- K5: fused softmax + gather + ELU (half-warp per dst, float4) ----
__global__ void __launch_bounds__(256) k_aggr(float* __restrict__ out) {
    const int gid  = blockIdx.x * blockDim.x + threadIdx.x;
    const int node = gid >> 4;
    if (node >= N_NODES) return;
    const int lane = threadIdx.x & 31;
    const int l    = lane & 15;
    const int sub  = lane >> 4;
    const unsigned gmask = 0xFFFFu << (16 * sub);

    const int beg = g_off[node];
    const int end = g_off[node + 1];
    const float erd = g_er[node];

    // ---- pass A: online softmax ----
    const float NEG_INF = __int_as_float(0xff800000);
    float m = NEG_INF, s = 0.0f;
    for (int j = beg + l; j < end; j += 16) {
        int sn = g_csr[j];
        float e = g_el[sn] + erd;
        e = (e >= 0.0f) ? e : LEAKY * e;
        float mn = fmaxf(m, e);
        s = s * __expf(m - mn) + __expf(e - mn);
        m = mn;
    }
#pragma unroll
    for (int o = 8; o; o >>= 1) {
        float mo = __shfl_xor_sync(gmask, m, o);
        float so = __shfl_xor_sync(gmask, s, o);
        float mn = fmaxf(m, mo);
        float sa = (m  == NEG_INF) ? 0.0f : s  * __expf(m  - mn);
        float sb = (mo == NEG_INF) ? 0.0f : so * __expf(mo - mn);
        s = sa + sb;
        m = mn;
    }
    float rs = (s > 0.0f) ? (1.0f / s) : 0.0f;

    // ---- pass B: weighted float4 gather, bound-free main loop (MLP=16) ----
    float4 acc = make_float4(0.f, 0.f, 0.f, 0.f);
    int j0 = beg;
    for (; j0 + 16 <= end; j0 += 16) {
        int sn = g_csr[j0 + l];
        float e = g_el[sn] + erd;
        e = (e >= 0.0f) ? e : LEAKY * e;
        float ax = __expf(e - m) * rs;
#pragma unroll
        for (int t = 0; t < 16; t++) {
            int   sj = __shfl_sync(gmask, sn, 16 * sub + t);
            float aj = __shfl_sync(gmask, ax, 16 * sub + t);
            float4 v = ((const float4*)(g_z + (size_t)sj * OUT_DIM))[l];
            acc.x += aj * v.x;
            acc.y += aj * v.y;
            acc.z += aj * v.z;
            acc.w += aj * v.w;
        }
    }
    if (j0 < end) {
        int j = j0 + l;
        int sn = 0;
        float ax = 0.0f;
        if (j < end) {
            sn = g_csr[j];
            float e = g_el[sn] + erd;
            e = (e >= 0.0f) ? e : LEAKY * e;
            ax = __expf(e - m) * rs;
        }
        int cnt = end - j0;
        for (int t = 0; t < cnt; t++) {
            int   sj = __shfl_sync(gmask, sn, 16 * sub + t);
            float aj = __shfl_sync(gmask, ax, 16 * sub + t);
            float4 v = ((const float4*)(g_z + (size_t)sj * OUT_DIM))[l];
            acc.x += aj * v.x;
            acc.y += aj * v.y;
            acc.z += aj * v.z;
            acc.w += aj * v.w;
        }
    }

    // ---- fused ELU + store ----
    acc.x = (acc.x > 0.0f) ? acc.x : expm1f(acc.x);
    acc.y = (acc.y > 0.0f) ? acc.y : expm1f(acc.y);
    acc.z = (acc.z > 0.0f) ? acc.z : expm1f(acc.z);
    acc.w = (acc.w > 0.0f) ? acc.w : expm1f(acc.w);
    ((float4*)(out + (size_t)node * OUT_DIM))[l] = acc;
}

// ---------------- launch ----------------
extern "C" void kernel_launch(void* const* d_in, const int* in_sizes, int n_in,
                              void* d_out, int out_size) {
    const float* h      = (const float*)d_in[0];
    const float* W_fc   = (const float*)d_in[1];
    const float* a_attn = (const float*)d_in[2];
    const int*   e_src  = (const int*)d_in[3];
    const int*   e_dst  = (const int*)d_in[4];
    float* out = (float*)d_out;

    k_gemm<<<(N_NODES + 127) / 128, 256>>>(h, W_fc, a_attn);
    k_hist<<<(N_EDGES + 255) / 256, 256>>>(e_dst);
    k_scan<<<NCHUNKS, SCAN_CHUNK>>>();
    k_scatter<<<(N_EDGES + 255) / 256, 256>>>(e_src, e_dst);
    k_aggr<<<(N_NODES * 16 + 255) / 256, 256>>>(out);
}

// round 7
// speedup vs baseline: 1.2139x; 1.2139x over previous
#include <cuda_runtime.h>
#include <math.h>
#include <stdint.h>

#define N_NODES 100000
#define N_EDGES 1600000
#define IN_DIM  256
#define OUT_DIM 64
#define LEAKY   0.01f

#define SCAN_CHUNK 1024
#define NCHUNKS ((N_NODES + SCAN_CHUNK - 1) / SCAN_CHUNK)   // 98

// ---------------- scratch ----------------
__device__ float g_z   [N_NODES * OUT_DIM];   // 25.6 MB (L2-resident)
__device__ float g_el  [N_NODES];
__device__ float g_er  [N_NODES];
__device__ int   g_cnt [N_NODES];
__device__ int   g_off [N_NODES + 1];
__device__ int   g_rank[N_EDGES];             // within-destination rank of each edge
__device__ int   g_bsum[NCHUNKS];
__device__ int   g_csr [N_EDGES];             // src ids, dst-sorted

// ---------------- helpers ----------------
__device__ __forceinline__ float cvt_tf32(float x) {
    uint32_t o;
    asm("cvt.rna.tf32.f32 %0, %1;" : "=r"(o) : "f"(x));
    return __uint_as_float(o);
}

__device__ __forceinline__ float4 cvt_tf32_v4(float4 v) {
    v.x = cvt_tf32(v.x); v.y = cvt_tf32(v.y);
    v.z = cvt_tf32(v.z); v.w = cvt_tf32(v.w);
    return v;
}

__device__ __forceinline__ void mma_tf32(float& d0, float& d1, float& d2, float& d3,
                                         uint32_t a0, uint32_t a1, uint32_t a2, uint32_t a3,
                                         uint32_t b0, uint32_t b1) {
    asm volatile("mma.sync.aligned.m16n8k8.row.col.f32.tf32.tf32.f32 "
                 "{%0,%1,%2,%3}, {%4,%5,%6,%7}, {%8,%9}, {%0,%1,%2,%3};"
                 : "+f"(d0), "+f"(d1), "+f"(d2), "+f"(d3)
                 : "r"(a0), "r"(a1), "r"(a2), "r"(a3), "r"(b0), "r"(b1));
}

// ---------------- K0: zero histogram ----------------
__global__ void k_zero() {
    int i = blockIdx.x * blockDim.x + threadIdx.x;
    if (i < N_NODES) g_cnt[i] = 0;
}

// ---------------- K1: tensor-core GEMM with register-staged pipeline (R4) -------
__global__ void __launch_bounds__(256) k_gemm(const float* __restrict__ h,
                                              const float* __restrict__ W,
                                              const float* __restrict__ a_attn) {
    __shared__ float As[128][36];   // pad 36: conflict-free A frag loads
    __shared__ float Bs[32][72];    // pad 72: conflict-free B frag loads

    const int tid  = threadIdx.x;
    const int warp = tid >> 5;
    const int lane = tid & 31;
    const int m0   = blockIdx.x * 128;
    const int wrow = warp * 16;
    const int r = lane >> 2;        // 0..7
    const int c = lane & 3;         // 0..3

    int arow[4], akq[4];
#pragma unroll
    for (int i = 0; i < 4; i++) {
        int id = tid + i * 256;
        arow[i] = id >> 3;
        akq[i]  = id & 7;
    }
    int bkk[2], bnq[2];
#pragma unroll
    for (int i = 0; i < 2; i++) {
        int id = tid + i * 256;
        bkk[i] = id >> 4;
        bnq[i] = id & 15;
    }

    float d[8][4];
#pragma unroll
    for (int j = 0; j < 8; j++)
#pragma unroll
        for (int q = 0; q < 4; q++) d[j][q] = 0.0f;

    float4 ra[4], rb[2];

    // prologue: load chunk 0
#pragma unroll
    for (int i = 0; i < 4; i++) {
        float4 v = make_float4(0.f, 0.f, 0.f, 0.f);
        if (m0 + arow[i] < N_NODES)
            v = *(const float4*)(h + (size_t)(m0 + arow[i]) * IN_DIM + akq[i] * 4);
        ra[i] = cvt_tf32_v4(v);
    }
#pragma unroll
    for (int i = 0; i < 2; i++)
        rb[i] = cvt_tf32_v4(*(const float4*)(W + (size_t)bkk[i] * OUT_DIM + bnq[i] * 4));

    for (int k0 = 0; k0 < IN_DIM; k0 += 32) {
#pragma unroll
        for (int i = 0; i < 4; i++)
            *(float4*)&As[arow[i]][akq[i] * 4] = ra[i];
#pragma unroll
        for (int i = 0; i < 2; i++)
            *(float4*)&Bs[bkk[i]][bnq[i] * 4] = rb[i];
        __syncthreads();

        int kn = k0 + 32;
        if (kn < IN_DIM) {
#pragma unroll
            for (int i = 0; i < 4; i++) {
                float4 v = make_float4(0.f, 0.f, 0.f, 0.f);
                if (m0 + arow[i] < N_NODES)
                    v = *(const float4*)(h + (size_t)(m0 + arow[i]) * IN_DIM + kn + akq[i] * 4);
                ra[i] = cvt_tf32_v4(v);
            }
#pragma unroll
            for (int i = 0; i < 2; i++)
                rb[i] = cvt_tf32_v4(*(const float4*)(W + (size_t)(kn + bkk[i]) * OUT_DIM + bnq[i] * 4));
        }

#pragma unroll
        for (int ks = 0; ks < 32; ks += 8) {
            uint32_t a0 = __float_as_uint(As[wrow + r    ][ks + c    ]);
            uint32_t a1 = __float_as_uint(As[wrow + r + 8][ks + c    ]);
            uint32_t a2 = __float_as_uint(As[wrow + r    ][ks + c + 4]);
            uint32_t a3 = __float_as_uint(As[wrow + r + 8][ks + c + 4]);
#pragma unroll
            for (int j = 0; j < 8; j++) {
                uint32_t b0 = __float_as_uint(Bs[ks + c    ][8 * j + r]);
                uint32_t b1 = __float_as_uint(Bs[ks + c + 4][8 * j + r]);
                mma_tf32(d[j][0], d[j][1], d[j][2], d[j][3], a0, a1, a2, a3, b0, b1);
            }
        }
        __syncthreads();
    }

    // ---- epilogue: store z, compute el/er (rows unique per warp, no atomics) ----
    const int row_lo = m0 + wrow + r;
    const int row_hi = row_lo + 8;

    float pl0 = 0.f, pl1 = 0.f, pr0 = 0.f, pr1 = 0.f;
#pragma unroll
    for (int j = 0; j < 8; j++) {
        int n = 8 * j + 2 * c;
        float al0 = a_attn[n], al1 = a_attn[n + 1];
        float ar0 = a_attn[OUT_DIM + n], ar1 = a_attn[OUT_DIM + n + 1];
        pl0 += d[j][0] * al0 + d[j][1] * al1;
        pr0 += d[j][0] * ar0 + d[j][1] * ar1;
        pl1 += d[j][2] * al0 + d[j][3] * al1;
        pr1 += d[j][2] * ar0 + d[j][3] * ar1;
        if (row_lo < N_NODES)
            *(float2*)(g_z + (size_t)row_lo * OUT_DIM + n) = make_float2(d[j][0], d[j][1]);
        if (row_hi < N_NODES)
            *(float2*)(g_z + (size_t)row_hi * OUT_DIM + n) = make_float2(d[j][2], d[j][3]);
    }
#pragma unroll
    for (int o = 1; o <= 2; o <<= 1) {
        pl0 += __shfl_xor_sync(0xffffffffu, pl0, o);
        pl1 += __shfl_xor_sync(0xffffffffu, pl1, o);
        pr0 += __shfl_xor_sync(0xffffffffu, pr0, o);
        pr1 += __shfl_xor_sync(0xffffffffu, pr1, o);
    }
    if (c == 0) {
        if (row_lo < N_NODES) { g_el[row_lo] = pl0; g_er[row_lo] = pr0; }
        if (row_hi < N_NODES) { g_el[row_hi] = pl1; g_er[row_hi] = pr1; }
    }
}

// ---------------- K2: histogram of dst + edge rank capture ----------------
__global__ void k_hist(const int* __restrict__ dst) {
    int i = blockIdx.x * blockDim.x + threadIdx.x;
    if (i >= N_EDGES) return;
    g_rank[i] = atomicAdd(&g_cnt[dst[i]], 1);
}

// ---------------- K3a: per-chunk exclusive scan (warp-shuffle, 2 barriers) ------
__global__ void __launch_bounds__(SCAN_CHUNK) k_scan1() {
    __shared__ int wsum[32];
    const int tid  = threadIdx.x;
    const int lane = tid & 31;
    const int w    = tid >> 5;
    const int i    = blockIdx.x * SCAN_CHUNK + tid;

    int x = (i < N_NODES) ? g_cnt[i] : 0;
    int v = x;
#pragma unroll
    for (int o = 1; o < 32; o <<= 1) {
        int t = __shfl_up_sync(0xffffffffu, v, o);
        if (lane >= o) v += t;
    }
    if (lane == 31) wsum[w] = v;
    __syncthreads();
    if (w == 0) {
        int y = wsum[lane];
#pragma unroll
        for (int o = 1; o < 32; o <<= 1) {
            int t = __shfl_up_sync(0xffffffffu, y, o);
            if (lane >= o) y += t;
        }
        wsum[lane] = y;   // inclusive warp sums
    }
    __syncthreads();
    int base = (w > 0) ? wsum[w - 1] : 0;
    int incl = v + base;
    if (i < N_NODES) g_off[i] = incl - x;          // exclusive within chunk
    if (tid == SCAN_CHUNK - 1) g_bsum[blockIdx.x] = incl;
}

// ---------------- K3b: scan chunk totals (single block) ----------------
__global__ void k_scan2() {
    __shared__ int sh[128];
    int tid = threadIdx.x;
    int x = (tid < NCHUNKS) ? g_bsum[tid] : 0;
    sh[tid] = x;
    __syncthreads();
#pragma unroll
    for (int off = 1; off < 128; off <<= 1) {
        int v = (tid >= off) ? sh[tid - off] : 0;
        __syncthreads();
        sh[tid] += v;
        __syncthreads();
    }
    if (tid < NCHUNKS) g_bsum[tid] = sh[tid] - x;  // exclusive
    if (tid == 0) g_off[N_NODES] = N_EDGES;
}

// ---------------- K3c: add chunk offsets ----------------
__global__ void k_scan3() {
    int i = blockIdx.x * blockDim.x + threadIdx.x;
    if (i < N_NODES) g_off[i] += g_bsum[i / SCAN_CHUNK];
}

// ---------------- K4: atomic-free scatter (rank precomputed in hist) ------------
__global__ void k_scatter(const int* __restrict__ src, const int* __restrict__ dst) {
    int i = blockIdx.x * blockDim.x + threadIdx.x;
    if (i >= N_EDGES) return;
    int d = dst[i];
    g_csr[g_off[d] + g_rank[i]] = src[i];
}

// ---------------- K5: fused softmax + gather + ELU (half-warp per dst, float4) --
__global__ void __launch_bounds__(256) k_aggr(float* __restrict__ out) {
    const int gid  = blockIdx.x * blockDim.x + threadIdx.x;
    const int node = gid >> 4;
    if (node >= N_NODES) return;
    const int lane = threadIdx.x & 31;
    const int l    = lane & 15;                     // lane within 16-group
    const int sub  = (lane >> 4);                   // which half-warp
    const unsigned gmask = 0xFFFFu << (16 * sub);   // group mask

    const int beg = g_off[node];
    const int end = g_off[node + 1];
    const float erd = g_er[node];

    // ---- pass A: online softmax over the group's edges ----
    const float NEG_INF = __int_as_float(0xff800000);
    float m = NEG_INF, s = 0.0f;
    for (int j = beg + l; j < end; j += 16) {
        int sn = g_csr[j];
        float e = __ldg(&g_el[sn]) + erd;
        e = (e >= 0.0f) ? e : LEAKY * e;
        float mn = fmaxf(m, e);
        s = s * __expf(m - mn) + __expf(e - mn);
        m = mn;
    }
#pragma unroll
    for (int o = 8; o; o >>= 1) {
        float mo = __shfl_xor_sync(gmask, m, o);
        float so = __shfl_xor_sync(gmask, s, o);
        float mn = fmaxf(m, mo);
        float sa = (m  == NEG_INF) ? 0.0f : s  * __expf(m  - mn);
        float sb = (mo == NEG_INF) ? 0.0f : so * __expf(mo - mn);
        s = sa + sb;
        m = mn;
    }
    float rs = (s > 0.0f) ? (1.0f / s) : 0.0f;

    // ---- pass B: weighted float4 gather (1 LDG.128 per lane per edge) ----
    float4 acc = make_float4(0.f, 0.f, 0.f, 0.f);
    for (int j0 = beg; j0 < end; j0 += 16) {
        int j = j0 + l;
        int sn = 0;
        float ax = 0.0f;
        if (j < end) {
            sn = g_csr[j];
            float e = __ldg(&g_el[sn]) + erd;
            e = (e >= 0.0f) ? e : LEAKY * e;
            ax = __expf(e - m) * rs;
        }
        int cnt = min(16, end - j0);
#pragma unroll 4
        for (int t = 0; t < cnt; t++) {
            int   sj = __shfl_sync(gmask, sn, 16 * sub + t);
            float aj = __shfl_sync(gmask, ax, 16 * sub + t);
            float4 v = __ldg(((const float4*)(g_z + (size_t)sj * OUT_DIM)) + l);
            acc.x += aj * v.x;
            acc.y += aj * v.y;
            acc.z += aj * v.z;
            acc.w += aj * v.w;
        }
    }

    // ---- fused ELU + store (16 lanes x float4 = 64 floats) ----
    acc.x = (acc.x > 0.0f) ? acc.x : expm1f(acc.x);
    acc.y = (acc.y > 0.0f) ? acc.y : expm1f(acc.y);
    acc.z = (acc.z > 0.0f) ? acc.z : expm1f(acc.z);
    acc.w = (acc.w > 0.0f) ? acc.w : expm1f(acc.w);
    ((float4*)(out + (size_t)node * OUT_DIM))[l] = acc;
}

// ---------------- launch ----------------
extern "C" void kernel_launch(void* const* d_in, const int* in_sizes, int n_in,
                              void* d_out, int out_size) {
    const float* h      = (const float*)d_in[0];
    const float* W_fc   = (const float*)d_in[1];
    const float* a_attn = (const float*)d_in[2];
    const int*   e_src  = (const int*)d_in[3];
    const int*   e_dst  = (const int*)d_in[4];
    float* out = (float*)d_out;

    k_zero<<<(N_NODES + 255) / 256, 256>>>();
    k_gemm<<<(N_NODES + 127) / 128, 256>>>(h, W_fc, a_attn);
    k_hist<<<(N_EDGES + 255) / 256, 256>>>(e_dst);
    k_scan1<<<NCHUNKS, SCAN_CHUNK>>>();
    k_scan2<<<1, 128>>>();
    k_scan3<<<(N_NODES + 255) / 256, 256>>>();
    k_scatter<<<(N_EDGES + 255) / 256, 256>>>(e_src, e_dst);
    k_aggr<<<(N_NODES * 16 + 255) / 256, 256>>>(out);
}

// round 8
// speedup vs baseline: 1.2156x; 1.0014x over previous
#include <cuda_runtime.h>
#include <math.h>
#include <stdint.h>

#define N_NODES 100000
#define N_EDGES 1600000
#define IN_DIM  256
#define OUT_DIM 64
#define LEAKY   0.01f

#define SCAN_CHUNK 1024
#define NCHUNKS ((N_NODES + SCAN_CHUNK - 1) / SCAN_CHUNK)   // 98

// ---------------- scratch ----------------
__device__ float g_z   [N_NODES * OUT_DIM];   // 25.6 MB (L2-resident)
__device__ float g_el  [N_NODES];
__device__ float g_er  [N_NODES];
__device__ int   g_cnt [N_NODES];
__device__ int   g_off [N_NODES + 1];
__device__ int   g_rank[N_EDGES];             // within-destination rank of each edge
__device__ int   g_bsum[NCHUNKS];
__device__ int   g_csr [N_EDGES];             // src ids, dst-sorted

// ---------------- helpers ----------------
__device__ __forceinline__ float cvt_tf32(float x) {
    uint32_t o;
    asm("cvt.rna.tf32.f32 %0, %1;" : "=r"(o) : "f"(x));
    return __uint_as_float(o);
}

__device__ __forceinline__ float4 cvt_tf32_v4(float4 v) {
    v.x = cvt_tf32(v.x); v.y = cvt_tf32(v.y);
    v.z = cvt_tf32(v.z); v.w = cvt_tf32(v.w);
    return v;
}

__device__ __forceinline__ void mma_tf32(float& d0, float& d1, float& d2, float& d3,
                                         uint32_t a0, uint32_t a1, uint32_t a2, uint32_t a3,
                                         uint32_t b0, uint32_t b1) {
    asm volatile("mma.sync.aligned.m16n8k8.row.col.f32.tf32.tf32.f32 "
                 "{%0,%1,%2,%3}, {%4,%5,%6,%7}, {%8,%9}, {%0,%1,%2,%3};"
                 : "+f"(d0), "+f"(d1), "+f"(d2), "+f"(d3)
                 : "r"(a0), "r"(a1), "r"(a2), "r"(a3), "r"(b0), "r"(b1));
}

// ---------------- K0: zero histogram ----------------
__global__ void k_zero() {
    int i = blockIdx.x * blockDim.x + threadIdx.x;
    if (i < N_NODES) g_cnt[i] = 0;
}

// ---------------- K1: tensor-core GEMM (R4 structure) + fused dst-histogram ------
__global__ void __launch_bounds__(256) k_gemm(const float* __restrict__ h,
                                              const float* __restrict__ W,
                                              const float* __restrict__ a_attn,
                                              const int* __restrict__ edst) {
    __shared__ float As[128][36];   // pad 36: conflict-free A frag loads
    __shared__ float Bs[32][72];    // pad 72: conflict-free B frag loads

    const int tid  = threadIdx.x;
    const int warp = tid >> 5;
    const int lane = tid & 31;
    const int m0   = blockIdx.x * 128;
    const int wrow = warp * 16;
    const int r = lane >> 2;        // 0..7
    const int c = lane & 3;         // 0..3

    int arow[4], akq[4];
#pragma unroll
    for (int i = 0; i < 4; i++) {
        int id = tid + i * 256;
        arow[i] = id >> 3;
        akq[i]  = id & 7;
    }
    int bkk[2], bnq[2];
#pragma unroll
    for (int i = 0; i < 2; i++) {
        int id = tid + i * 256;
        bkk[i] = id >> 4;
        bnq[i] = id & 15;
    }

    float d[8][4];
#pragma unroll
    for (int j = 0; j < 8; j++)
#pragma unroll
        for (int q = 0; q < 4; q++) d[j][q] = 0.0f;

    float4 ra[4], rb[2];

    // prologue: load chunk 0
#pragma unroll
    for (int i = 0; i < 4; i++) {
        float4 v = make_float4(0.f, 0.f, 0.f, 0.f);
        if (m0 + arow[i] < N_NODES)
            v = *(const float4*)(h + (size_t)(m0 + arow[i]) * IN_DIM + akq[i] * 4);
        ra[i] = cvt_tf32_v4(v);
    }
#pragma unroll
    for (int i = 0; i < 2; i++)
        rb[i] = cvt_tf32_v4(*(const float4*)(W + (size_t)bkk[i] * OUT_DIM + bnq[i] * 4));

    for (int k0 = 0; k0 < IN_DIM; k0 += 32) {
#pragma unroll
        for (int i = 0; i < 4; i++)
            *(float4*)&As[arow[i]][akq[i] * 4] = ra[i];
#pragma unroll
        for (int i = 0; i < 2; i++)
            *(float4*)&Bs[bkk[i]][bnq[i] * 4] = rb[i];
        __syncthreads();

        int kn = k0 + 32;
        if (kn < IN_DIM) {
#pragma unroll
            for (int i = 0; i < 4; i++) {
                float4 v = make_float4(0.f, 0.f, 0.f, 0.f);
                if (m0 + arow[i] < N_NODES)
                    v = *(const float4*)(h + (size_t)(m0 + arow[i]) * IN_DIM + kn + akq[i] * 4);
                ra[i] = cvt_tf32_v4(v);
            }
#pragma unroll
            for (int i = 0; i < 2; i++)
                rb[i] = cvt_tf32_v4(*(const float4*)(W + (size_t)(kn + bkk[i]) * OUT_DIM + bnq[i] * 4));
        }

#pragma unroll
        for (int ks = 0; ks < 32; ks += 8) {
            uint32_t a0 = __float_as_uint(As[wrow + r    ][ks + c    ]);
            uint32_t a1 = __float_as_uint(As[wrow + r + 8][ks + c    ]);
            uint32_t a2 = __float_as_uint(As[wrow + r    ][ks + c + 4]);
            uint32_t a3 = __float_as_uint(As[wrow + r + 8][ks + c + 4]);
#pragma unroll
            for (int j = 0; j < 8; j++) {
                uint32_t b0 = __float_as_uint(Bs[ks + c    ][8 * j + r]);
                uint32_t b1 = __float_as_uint(Bs[ks + c + 4][8 * j + r]);
                mma_tf32(d[j][0], d[j][1], d[j][2], d[j][3], a0, a1, a2, a3, b0, b1);
            }
        }
        __syncthreads();
    }

    // ---- epilogue: store z, compute el/er (rows unique per warp, no atomics) ----
    const int row_lo = m0 + wrow + r;
    const int row_hi = row_lo + 8;

    float pl0 = 0.f, pl1 = 0.f, pr0 = 0.f, pr1 = 0.f;
#pragma unroll
    for (int j = 0; j < 8; j++) {
        int n = 8 * j + 2 * c;
        float al0 = a_attn[n], al1 = a_attn[n + 1];
        float ar0 = a_attn[OUT_DIM + n], ar1 = a_attn[OUT_DIM + n + 1];
        pl0 += d[j][0] * al0 + d[j][1] * al1;
        pr0 += d[j][0] * ar0 + d[j][1] * ar1;
        pl1 += d[j][2] * al0 + d[j][3] * al1;
        pr1 += d[j][2] * ar0 + d[j][3] * ar1;
        if (row_lo < N_NODES)
            *(float2*)(g_z + (size_t)row_lo * OUT_DIM + n) = make_float2(d[j][0], d[j][1]);
        if (row_hi < N_NODES)
            *(float2*)(g_z + (size_t)row_hi * OUT_DIM + n) = make_float2(d[j][2], d[j][3]);
    }
#pragma unroll
    for (int o = 1; o <= 2; o <<= 1) {
        pl0 += __shfl_xor_sync(0xffffffffu, pl0, o);
        pl1 += __shfl_xor_sync(0xffffffffu, pl1, o);
        pr0 += __shfl_xor_sync(0xffffffffu, pr0, o);
        pr1 += __shfl_xor_sync(0xffffffffu, pr1, o);
    }
    if (c == 0) {
        if (row_lo < N_NODES) { g_el[row_lo] = pl0; g_er[row_lo] = pr0; }
        if (row_hi < N_NODES) { g_el[row_hi] = pl1; g_er[row_hi] = pr1; }
    }

    // ---- fused dst-histogram + rank capture (independent of GEMM data) ----------
    // k_zero completed before this kernel launched (stream order), so g_cnt is 0.
    {
        const int T   = gridDim.x * 256;
        for (int e = blockIdx.x * 256 + tid; e < N_EDGES; e += T) {
            g_rank[e] = atomicAdd(&g_cnt[edst[e]], 1);
        }
    }
}

// ---------------- K3a: per-chunk exclusive scan (warp-shuffle, 2 barriers) ------
__global__ void __launch_bounds__(SCAN_CHUNK) k_scan1() {
    __shared__ int wsum[32];
    const int tid  = threadIdx.x;
    const int lane = tid & 31;
    const int w    = tid >> 5;
    const int i    = blockIdx.x * SCAN_CHUNK + tid;

    int x = (i < N_NODES) ? g_cnt[i] : 0;
    int v = x;
#pragma unroll
    for (int o = 1; o < 32; o <<= 1) {
        int t = __shfl_up_sync(0xffffffffu, v, o);
        if (lane >= o) v += t;
    }
    if (lane == 31) wsum[w] = v;
    __syncthreads();
    if (w == 0) {
        int y = wsum[lane];
#pragma unroll
        for (int o = 1; o < 32; o <<= 1) {
            int t = __shfl_up_sync(0xffffffffu, y, o);
            if (lane >= o) y += t;
        }
        wsum[lane] = y;   // inclusive warp sums
    }
    __syncthreads();
    int base = (w > 0) ? wsum[w - 1] : 0;
    int incl = v + base;
    if (i < N_NODES) g_off[i] = incl - x;          // exclusive within chunk
    if (tid == SCAN_CHUNK - 1) g_bsum[blockIdx.x] = incl;
}

// ---------------- K3b: scan chunk totals (single block) ----------------
__global__ void k_scan2() {
    __shared__ int sh[128];
    int tid = threadIdx.x;
    int x = (tid < NCHUNKS) ? g_bsum[tid] : 0;
    sh[tid] = x;
    __syncthreads();
#pragma unroll
    for (int off = 1; off < 128; off <<= 1) {
        int v = (tid >= off) ? sh[tid - off] : 0;
        __syncthreads();
        sh[tid] += v;
        __syncthreads();
    }
    if (tid < NCHUNKS) g_bsum[tid] = sh[tid] - x;  // exclusive
    if (tid == 0) g_off[N_NODES] = N_EDGES;
}

// ---------------- K3c: add chunk offsets ----------------
__global__ void k_scan3() {
    int i = blockIdx.x * blockDim.x + threadIdx.x;
    if (i < N_NODES) g_off[i] += g_bsum[i / SCAN_CHUNK];
}

// ---------------- K4: atomic-free scatter (rank precomputed in gemm tail) -------
__global__ void k_scatter(const int* __restrict__ src, const int* __restrict__ dst) {
    int i = blockIdx.x * blockDim.x + threadIdx.x;
    if (i >= N_EDGES) return;
    int d = dst[i];
    g_csr[g_off[d] + g_rank[i]] = src[i];
}

// ---------------- K5: fused softmax + gather + ELU (half-warp per dst, float4) --
__global__ void __launch_bounds__(256) k_aggr(float* __restrict__ out) {
    const int gid  = blockIdx.x * blockDim.x + threadIdx.x;
    const int node = gid >> 4;
    if (node >= N_NODES) return;
    const int lane = threadIdx.x & 31;
    const int l    = lane & 15;                     // lane within 16-group
    const int sub  = (lane >> 4);                   // which half-warp
    const unsigned gmask = 0xFFFFu << (16 * sub);   // group mask

    const int beg = g_off[node];
    const int end = g_off[node + 1];
    const float erd = g_er[node];

    // ---- pass A: online softmax over the group's edges ----
    const float NEG_INF = __int_as_float(0xff800000);
    float m = NEG_INF, s = 0.0f;
    for (int j = beg + l; j < end; j += 16) {
        int sn = g_csr[j];
        float e = __ldg(&g_el[sn]) + erd;
        e = (e >= 0.0f) ? e : LEAKY * e;
        float mn = fmaxf(m, e);
        s = s * __expf(m - mn) + __expf(e - mn);
        m = mn;
    }
#pragma unroll
    for (int o = 8; o; o >>= 1) {
        float mo = __shfl_xor_sync(gmask, m, o);
        float so = __shfl_xor_sync(gmask, s, o);
        float mn = fmaxf(m, mo);
        float sa = (m  == NEG_INF) ? 0.0f : s  * __expf(m  - mn);
        float sb = (mo == NEG_INF) ? 0.0f : so * __expf(mo - mn);
        s = sa + sb;
        m = mn;
    }
    float rs = (s > 0.0f) ? (1.0f / s) : 0.0f;

    // ---- pass B: weighted float4 gather (1 LDG.128 per lane per edge) ----
    float4 acc = make_float4(0.f, 0.f, 0.f, 0.f);
    for (int j0 = beg; j0 < end; j0 += 16) {
        int j = j0 + l;
        int sn = 0;
        float ax = 0.0f;
        if (j < end) {
            sn = g_csr[j];
            float e = __ldg(&g_el[sn]) + erd;
            e = (e >= 0.0f) ? e : LEAKY * e;
            ax = __expf(e - m) * rs;
        }
        int cnt = min(16, end - j0);
#pragma unroll 4
        for (int t = 0; t < cnt; t++) {
            int   sj = __shfl_sync(gmask, sn, 16 * sub + t);
            float aj = __shfl_sync(gmask, ax, 16 * sub + t);
            float4 v = __ldg(((const float4*)(g_z + (size_t)sj * OUT_DIM)) + l);
            acc.x += aj * v.x;
            acc.y += aj * v.y;
            acc.z += aj * v.z;
            acc.w += aj * v.w;
        }
    }

    // ---- fused ELU + store (16 lanes x float4 = 64 floats) ----
    acc.x = (acc.x > 0.0f) ? acc.x : expm1f(acc.x);
    acc.y = (acc.y > 0.0f) ? acc.y : expm1f(acc.y);
    acc.z = (acc.z > 0.0f) ? acc.z : expm1f(acc.z);
    acc.w = (acc.w > 0.0f) ? acc.w : expm1f(acc.w);
    ((float4*)(out + (size_t)node * OUT_DIM))[l] = acc;
}

// ---------------- launch ----------------
extern "C" void kernel_launch(void* const* d_in, const int* in_sizes, int n_in,
                              void* d_out, int out_size) {
    const float* h      = (const float*)d_in[0];
    const float* W_fc   = (const float*)d_in[1];
    const float* a_attn = (const float*)d_in[2];
    const int*   e_src  = (const int*)d_in[3];
    const int*   e_dst  = (const int*)d_in[4];
    float* out = (float*)d_out;

    k_zero<<<(N_NODES + 255) / 256, 256>>>();
    k_gemm<<<(N_NODES + 127) / 128, 256>>>(h, W_fc, a_attn, e_dst);
    k_scan1<<<NCHUNKS, SCAN_CHUNK>>>();
    k_scan2<<<1, 128>>>();
    k_scan3<<<(N_NODES + 255) / 256, 256>>>();
    k_scatter<<<(N_EDGES + 255) / 256, 256>>>(e_src, e_dst);
    k_aggr<<<(N_NODES * 16 + 255) / 256, 256>>>(out);
}

// round 9
// speedup vs baseline: 1.2881x; 1.0596x over previous
#include <cuda_runtime.h>
#include <math.h>
#include <stdint.h>

#define N_NODES 100000
#define N_EDGES 1600000
#define IN_DIM  256
#define OUT_DIM 64
#define LEAKY   0.01f

#define SCAN_CHUNK 1024
#define NCHUNKS ((N_NODES + SCAN_CHUNK - 1) / SCAN_CHUNK)   // 98

// ---------------- scratch ----------------
__device__ float g_z   [N_NODES * OUT_DIM];   // 25.6 MB (L2-resident)
__device__ float g_el  [N_NODES];
__device__ float g_er  [N_NODES];
__device__ int   g_cnt [N_NODES];
__device__ int   g_off [N_NODES + 1];
__device__ int   g_rank[N_EDGES];             // within-destination rank of each edge
__device__ int   g_bsum[NCHUNKS];
__device__ int   g_csr [N_EDGES];             // src ids, dst-sorted

// ---------------- helpers ----------------
__device__ __forceinline__ float cvt_tf32(float x) {
    uint32_t o;
    asm("cvt.rna.tf32.f32 %0, %1;" : "=r"(o) : "f"(x));
    return __uint_as_float(o);
}

__device__ __forceinline__ float4 cvt_tf32_v4(float4 v) {
    v.x = cvt_tf32(v.x); v.y = cvt_tf32(v.y);
    v.z = cvt_tf32(v.z); v.w = cvt_tf32(v.w);
    return v;
}

__device__ __forceinline__ void mma_tf32(float& d0, float& d1, float& d2, float& d3,
                                         uint32_t a0, uint32_t a1, uint32_t a2, uint32_t a3,
                                         uint32_t b0, uint32_t b1) {
    asm volatile("mma.sync.aligned.m16n8k8.row.col.f32.tf32.tf32.f32 "
                 "{%0,%1,%2,%3}, {%4,%5,%6,%7}, {%8,%9}, {%0,%1,%2,%3};"
                 : "+f"(d0), "+f"(d1), "+f"(d2), "+f"(d3)
                 : "r"(a0), "r"(a1), "r"(a2), "r"(a3), "r"(b0), "r"(b1));
}

// ---------------- K0: zero histogram ----------------
__global__ void k_zero() {
    int i = blockIdx.x * blockDim.x + threadIdx.x;
    if (i < N_NODES) g_cnt[i] = 0;
}

// ---------------- K1: tensor-core GEMM (R4 structure) + fused dst-histogram ------
__global__ void __launch_bounds__(256) k_gemm(const float* __restrict__ h,
                                              const float* __restrict__ W,
                                              const float* __restrict__ a_attn,
                                              const int* __restrict__ edst) {
    __shared__ float As[128][36];   // pad 36: conflict-free A frag loads
    __shared__ float Bs[32][72];    // pad 72: conflict-free B frag loads

    const int tid  = threadIdx.x;
    const int warp = tid >> 5;
    const int lane = tid & 31;
    const int m0   = blockIdx.x * 128;
    const int wrow = warp * 16;
    const int r = lane >> 2;        // 0..7
    const int c = lane & 3;         // 0..3

    int arow[4], akq[4];
#pragma unroll
    for (int i = 0; i < 4; i++) {
        int id = tid + i * 256;
        arow[i] = id >> 3;
        akq[i]  = id & 7;
    }
    int bkk[2], bnq[2];
#pragma unroll
    for (int i = 0; i < 2; i++) {
        int id = tid + i * 256;
        bkk[i] = id >> 4;
        bnq[i] = id & 15;
    }

    float d[8][4];
#pragma unroll
    for (int j = 0; j < 8; j++)
#pragma unroll
        for (int q = 0; q < 4; q++) d[j][q] = 0.0f;

    float4 ra[4], rb[2];

    // prologue: load chunk 0
#pragma unroll
    for (int i = 0; i < 4; i++) {
        float4 v = make_float4(0.f, 0.f, 0.f, 0.f);
        if (m0 + arow[i] < N_NODES)
            v = *(const float4*)(h + (size_t)(m0 + arow[i]) * IN_DIM + akq[i] * 4);
        ra[i] = cvt_tf32_v4(v);
    }
#pragma unroll
    for (int i = 0; i < 2; i++)
        rb[i] = cvt_tf32_v4(*(const float4*)(W + (size_t)bkk[i] * OUT_DIM + bnq[i] * 4));

    for (int k0 = 0; k0 < IN_DIM; k0 += 32) {
#pragma unroll
        for (int i = 0; i < 4; i++)
            *(float4*)&As[arow[i]][akq[i] * 4] = ra[i];
#pragma unroll
        for (int i = 0; i < 2; i++)
            *(float4*)&Bs[bkk[i]][bnq[i] * 4] = rb[i];
        __syncthreads();

        int kn = k0 + 32;
        if (kn < IN_DIM) {
#pragma unroll
            for (int i = 0; i < 4; i++) {
                float4 v = make_float4(0.f, 0.f, 0.f, 0.f);
                if (m0 + arow[i] < N_NODES)
                    v = *(const float4*)(h + (size_t)(m0 + arow[i]) * IN_DIM + kn + akq[i] * 4);
                ra[i] = cvt_tf32_v4(v);
            }
#pragma unroll
            for (int i = 0; i < 2; i++)
                rb[i] = cvt_tf32_v4(*(const float4*)(W + (size_t)(kn + bkk[i]) * OUT_DIM + bnq[i] * 4));
        }

#pragma unroll
        for (int ks = 0; ks < 32; ks += 8) {
            uint32_t a0 = __float_as_uint(As[wrow + r    ][ks + c    ]);
            uint32_t a1 = __float_as_uint(As[wrow + r + 8][ks + c    ]);
            uint32_t a2 = __float_as_uint(As[wrow + r    ][ks + c + 4]);
            uint32_t a3 = __float_as_uint(As[wrow + r + 8][ks + c + 4]);
#pragma unroll
            for (int j = 0; j < 8; j++) {
                uint32_t b0 = __float_as_uint(Bs[ks + c    ][8 * j + r]);
                uint32_t b1 = __float_as_uint(Bs[ks + c + 4][8 * j + r]);
                mma_tf32(d[j][0], d[j][1], d[j][2], d[j][3], a0, a1, a2, a3, b0, b1);
            }
        }
        __syncthreads();
    }

    // ---- epilogue: store z, compute el/er (rows unique per warp, no atomics) ----
    const int row_lo = m0 + wrow + r;
    const int row_hi = row_lo + 8;

    float pl0 = 0.f, pl1 = 0.f, pr0 = 0.f, pr1 = 0.f;
#pragma unroll
    for (int j = 0; j < 8; j++) {
        int n = 8 * j + 2 * c;
        float al0 = a_attn[n], al1 = a_attn[n + 1];
        float ar0 = a_attn[OUT_DIM + n], ar1 = a_attn[OUT_DIM + n + 1];
        pl0 += d[j][0] * al0 + d[j][1] * al1;
        pr0 += d[j][0] * ar0 + d[j][1] * ar1;
        pl1 += d[j][2] * al0 + d[j][3] * al1;
        pr1 += d[j][2] * ar0 + d[j][3] * ar1;
        if (row_lo < N_NODES)
            *(float2*)(g_z + (size_t)row_lo * OUT_DIM + n) = make_float2(d[j][0], d[j][1]);
        if (row_hi < N_NODES)
            *(float2*)(g_z + (size_t)row_hi * OUT_DIM + n) = make_float2(d[j][2], d[j][3]);
    }
#pragma unroll
    for (int o = 1; o <= 2; o <<= 1) {
        pl0 += __shfl_xor_sync(0xffffffffu, pl0, o);
        pl1 += __shfl_xor_sync(0xffffffffu, pl1, o);
        pr0 += __shfl_xor_sync(0xffffffffu, pr0, o);
        pr1 += __shfl_xor_sync(0xffffffffu, pr1, o);
    }
    if (c == 0) {
        if (row_lo < N_NODES) { g_el[row_lo] = pl0; g_er[row_lo] = pr0; }
        if (row_hi < N_NODES) { g_el[row_hi] = pl1; g_er[row_hi] = pr1; }
    }

    // ---- fused dst-histogram + rank capture (independent of GEMM data) ----------
    {
        const int T = gridDim.x * 256;
        for (int e = blockIdx.x * 256 + tid; e < N_EDGES; e += T) {
            g_rank[e] = atomicAdd(&g_cnt[edst[e]], 1);
        }
    }
}

// ---------------- K3a: per-chunk exclusive scan (warp-shuffle, 2 barriers) ------
__global__ void __launch_bounds__(SCAN_CHUNK) k_scan1() {
    __shared__ int wsum[32];
    const int tid  = threadIdx.x;
    const int lane = tid & 31;
    const int w    = tid >> 5;
    const int i    = blockIdx.x * SCAN_CHUNK + tid;

    int x = (i < N_NODES) ? g_cnt[i] : 0;
    int v = x;
#pragma unroll
    for (int o = 1; o < 32; o <<= 1) {
        int t = __shfl_up_sync(0xffffffffu, v, o);
        if (lane >= o) v += t;
    }
    if (lane == 31) wsum[w] = v;
    __syncthreads();
    if (w == 0) {
        int y = wsum[lane];
#pragma unroll
        for (int o = 1; o < 32; o <<= 1) {
            int t = __shfl_up_sync(0xffffffffu, y, o);
            if (lane >= o) y += t;
        }
        wsum[lane] = y;   // inclusive warp sums
    }
    __syncthreads();
    int base = (w > 0) ? wsum[w - 1] : 0;
    int incl = v + base;
    if (i < N_NODES) g_off[i] = incl - x;          // exclusive within chunk
    if (tid == SCAN_CHUNK - 1) g_bsum[blockIdx.x] = incl;
}

// ---------------- K3b: scan chunk totals (single block) ----------------
__global__ void k_scan2() {
    __shared__ int sh[128];
    int tid = threadIdx.x;
    int x = (tid < NCHUNKS) ? g_bsum[tid] : 0;
    sh[tid] = x;
    __syncthreads();
#pragma unroll
    for (int off = 1; off < 128; off <<= 1) {
        int v = (tid >= off) ? sh[tid - off] : 0;
        __syncthreads();
        sh[tid] += v;
        __syncthreads();
    }
    if (tid < NCHUNKS) g_bsum[tid] = sh[tid] - x;  // exclusive
    if (tid == 0) g_off[N_NODES] = N_EDGES;
}

// ---------------- K3c: add chunk offsets ----------------
__global__ void k_scan3() {
    int i = blockIdx.x * blockDim.x + threadIdx.x;
    if (i < N_NODES) g_off[i] += g_bsum[i / SCAN_CHUNK];
}

// ---------------- K4: atomic-free scatter (rank precomputed in gemm tail) -------
__global__ void k_scatter(const int* __restrict__ src, const int* __restrict__ dst) {
    int i = blockIdx.x * blockDim.x + threadIdx.x;
    if (i >= N_EDGES) return;
    int d = dst[i];
    g_csr[g_off[d] + g_rank[i]] = src[i];
}

// ---------------- K5: SINGLE-PASS unnormalized softmax + gather + ELU -----------
// half-warp per dst. acc = sum(exp(e_j) * z_j); s = sum(exp(e_j)); out = elu(acc/s).
// Max-subtraction cancels exactly in the division; logits are O(few) so exp is safe.
__global__ void __launch_bounds__(256) k_aggr(float* __restrict__ out) {
    const int gid  = blockIdx.x * blockDim.x + threadIdx.x;
    const int node = gid >> 4;
    if (node >= N_NODES) return;
    const int lane = threadIdx.x & 31;
    const int l    = lane & 15;                     // lane within 16-group
    const int sub  = (lane >> 4);                   // which half-warp
    const unsigned gmask = 0xFFFFu << (16 * sub);   // group mask

    const int beg = g_off[node];
    const int end = g_off[node + 1];
    const float erd = g_er[node];

    float  s   = 0.0f;
    float4 acc = make_float4(0.f, 0.f, 0.f, 0.f);

    for (int j0 = beg; j0 < end; j0 += 16) {
        int j = j0 + l;
        int sn = 0;
        float ax = 0.0f;
        if (j < end) {
            sn = g_csr[j];
            float e = __ldg(&g_el[sn]) + erd;
            e = (e >= 0.0f) ? e : LEAKY * e;
            ax = __expf(e);
            s += ax;
        }
        int cnt = min(16, end - j0);
#pragma unroll 4
        for (int t = 0; t < cnt; t++) {
            int   sj = __shfl_sync(gmask, sn, 16 * sub + t);
            float aj = __shfl_sync(gmask, ax, 16 * sub + t);
            float4 v = __ldg(((const float4*)(g_z + (size_t)sj * OUT_DIM)) + l);
            acc.x += aj * v.x;
            acc.y += aj * v.y;
            acc.z += aj * v.z;
            acc.w += aj * v.w;
        }
    }

    // reduce s across the 16-lane group
#pragma unroll
    for (int o = 8; o; o >>= 1)
        s += __shfl_xor_sync(gmask, s, o);
    float rs = (s > 0.0f) ? (1.0f / s) : 0.0f;

    acc.x *= rs; acc.y *= rs; acc.z *= rs; acc.w *= rs;

    // ---- fused ELU + store (16 lanes x float4 = 64 floats) ----
    acc.x = (acc.x > 0.0f) ? acc.x : expm1f(acc.x);
    acc.y = (acc.y > 0.0f) ? acc.y : expm1f(acc.y);
    acc.z = (acc.z > 0.0f) ? acc.z : expm1f(acc.z);
    acc.w = (acc.w > 0.0f) ? acc.w : expm1f(acc.w);
    ((float4*)(out + (size_t)node * OUT_DIM))[l] = acc;
}

// ---------------- launch ----------------
extern "C" void kernel_launch(void* const* d_in, const int* in_sizes, int n_in,
                              void* d_out, int out_size) {
    const float* h      = (const float*)d_in[0];
    const float* W_fc   = (const float*)d_in[1];
    const float* a_attn = (const float*)d_in[2];
    const int*   e_src  = (const int*)d_in[3];
    const int*   e_dst  = (const int*)d_in[4];
    float* out = (float*)d_out;

    k_zero<<<(N_NODES + 255) / 256, 256>>>();
    k_gemm<<<(N_NODES + 127) / 128, 256>>>(h, W_fc, a_attn, e_dst);
    k_scan1<<<NCHUNKS, SCAN_CHUNK>>>();
    k_scan2<<<1, 128>>>();
    k_scan3<<<(N_NODES + 255) / 256, 256>>>();
    k_scatter<<<(N_EDGES + 255) / 256, 256>>>(e_src, e_dst);
    k_aggr<<<(N_NODES * 16 + 255) / 256, 256>>>(out);
}